// round 9
// baseline (speedup 1.0000x reference)
#include <cuda_runtime.h>
#include <cstdint>

#define BDIM      256
#define D_F4      64        // CODE_DIM/4
#define K_CENT    4
#define N_CLASSES 1000
#define MAXB      262144    // = 2^18; perm packs sidx in 18 bits
#define SPW       8         // sorted samples per warp in main kernel
#define CHUNK     2048
#define NCH_MAX   (MAXB / CHUNK)   // 128

// Scratch (static — no dynamic allocation allowed)
// g_hist[c][m]: counts per (class, chunk); rewritten in-place to global offsets by scan.
__device__ int g_hist[N_CLASSES][NCH_MAX];
__device__ int g_perm[MAXB];               // packed (cls<<18)|sidx, grouped by class

__device__ __forceinline__ int clamp_cls(int c) {
    return min(max(c, 0), N_CLASSES - 1);
}

// ---------------- pre-pass: radix-sort by class ----------------

// Per-chunk histogram; non-atomic global store (no zero kernel needed).
__global__ void __launch_bounds__(BDIM) hist_kernel(const int* __restrict__ pred, int B) {
    __shared__ int h[N_CLASSES];
    for (int i = threadIdx.x; i < N_CLASSES; i += BDIM) h[i] = 0;
    __syncthreads();
    const int start = blockIdx.x * CHUNK;
    const int end   = min(start + CHUNK, B);
    for (int i = start + threadIdx.x; i < end; i += BDIM)
        atomicAdd(&h[clamp_cls(__ldg(&pred[i]))], 1);
    __syncthreads();
    for (int i = threadIdx.x; i < N_CLASSES; i += BDIM)
        g_hist[i][blockIdx.x] = h[i];
}

// Single block: class totals -> exclusive scan of totals -> rewrite rows to offsets.
__global__ void __launch_bounds__(1024) scan_kernel(int nch) {
    __shared__ int s[1024];
    const int t = threadIdx.x;
    int total = 0;
    if (t < N_CLASSES)
        for (int m = 0; m < nch; ++m) total += g_hist[t][m];
    s[t] = (t < N_CLASSES) ? total : 0;
    __syncthreads();
    #pragma unroll
    for (int off = 1; off < 1024; off <<= 1) {
        int x = (t >= off) ? s[t - off] : 0;
        __syncthreads();
        s[t] += x;
        __syncthreads();
    }
    if (t < N_CLASSES) {
        int run = s[t] - total;            // exclusive class start
        for (int m = 0; m < nch; ++m) {
            int tmp = g_hist[t][m];
            g_hist[t][m] = run;            // global offset for (class, chunk)
            run += tmp;
        }
    }
}

// Per-chunk scatter with SMEM cursors (no global atomic contention).
__global__ void __launch_bounds__(BDIM) scatter_kernel(const int* __restrict__ pred, int B) {
    __shared__ int cur[N_CLASSES];
    const int b = blockIdx.x;
    for (int c = threadIdx.x; c < N_CLASSES; c += BDIM)
        cur[c] = g_hist[c][b];
    __syncthreads();
    const int start = b * CHUNK;
    const int end   = min(start + CHUNK, B);
    for (int i = start + threadIdx.x; i < end; i += BDIM) {
        int c = clamp_cls(__ldg(&pred[i]));
        int pos = atomicAdd(&cur[c], 1);   // smem atomic, spread addresses
        g_perm[pos] = (c << 18) | i;
    }
}

// ---------------- main kernel (sorted, register-cached centroids, pipelined) ----

__global__ void __launch_bounds__(BDIM) sorted_kernel(
    const float4* __restrict__ codes,      // [B, 64]
    const float4* __restrict__ cents,      // [1000, 4, 64]
    float* __restrict__ out,               // [B]
    int B)
{
    const int warp = (int)((blockIdx.x * (unsigned)BDIM + threadIdx.x) >> 5);
    const int lane = threadIdx.x & 31;
    const int base = warp * SPW;
    if (base >= B) return;
    const int n = min(SPW, B - base);

    // one coalesced LDG fetches this warp's SPW perm entries; shfl broadcasts per j
    const int p = __ldg(&g_perm[base + min(lane, n - 1)]);

    float4 c00, c01, c10, c11, c20, c21, c30, c31;
    int cached = -1;

    // prefetch sample 0's codes
    int pk   = __shfl_sync(0xFFFFFFFFu, p, 0);
    int sidx = pk & 0x3FFFF;
    float4 a0, a1;
    {
        const float4* __restrict__ cp = codes + (size_t)sidx * D_F4;
        a0 = __ldg(&cp[lane]);
        a1 = __ldg(&cp[lane + 32]);
    }

    for (int j = 0; j < n; ++j) {
        const int cls     = pk >> 18;      // warp-uniform within sorted runs
        const int out_idx = sidx;

        // ---- prefetch next sample's codes before this sample's reduce ----
        int npk = pk;
        float4 na0 = a0, na1 = a1;
        if (j + 1 < n) {
            npk = __shfl_sync(0xFFFFFFFFu, p, j + 1);
            const int ns = npk & 0x3FFFF;
            const float4* __restrict__ np = codes + (size_t)ns * D_F4;
            na0 = __ldg(&np[lane]);
            na1 = __ldg(&np[lane + 32]);
        }

        // ---- centroid register cache (warp-uniform branch; rare reload) ----
        if (cls != cached) {
            const float4* __restrict__ ct = cents + (size_t)cls * (K_CENT * D_F4);
            c00 = __ldg(&ct[0 * D_F4 + lane]);  c01 = __ldg(&ct[0 * D_F4 + lane + 32]);
            c10 = __ldg(&ct[1 * D_F4 + lane]);  c11 = __ldg(&ct[1 * D_F4 + lane + 32]);
            c20 = __ldg(&ct[2 * D_F4 + lane]);  c21 = __ldg(&ct[2 * D_F4 + lane + 32]);
            c30 = __ldg(&ct[3 * D_F4 + lane]);  c31 = __ldg(&ct[3 * D_F4 + lane + 32]);
            cached = cls;
        }

        float s0 = fabsf(a0.x - c00.x) + fabsf(a0.y - c00.y) + fabsf(a0.z - c00.z) + fabsf(a0.w - c00.w)
                 + fabsf(a1.x - c01.x) + fabsf(a1.y - c01.y) + fabsf(a1.z - c01.z) + fabsf(a1.w - c01.w);
        float s1 = fabsf(a0.x - c10.x) + fabsf(a0.y - c10.y) + fabsf(a0.z - c10.z) + fabsf(a0.w - c10.w)
                 + fabsf(a1.x - c11.x) + fabsf(a1.y - c11.y) + fabsf(a1.z - c11.z) + fabsf(a1.w - c11.w);
        float s2 = fabsf(a0.x - c20.x) + fabsf(a0.y - c20.y) + fabsf(a0.z - c20.z) + fabsf(a0.w - c20.w)
                 + fabsf(a1.x - c21.x) + fabsf(a1.y - c21.y) + fabsf(a1.z - c21.z) + fabsf(a1.w - c21.w);
        float s3 = fabsf(a0.x - c30.x) + fabsf(a0.y - c30.y) + fabsf(a0.z - c30.z) + fabsf(a0.w - c30.w)
                 + fabsf(a1.x - c31.x) + fabsf(a1.y - c31.y) + fabsf(a1.z - c31.z) + fabsf(a1.w - c31.w);

        #pragma unroll
        for (int off = 16; off > 0; off >>= 1) {
            s0 += __shfl_xor_sync(0xFFFFFFFFu, s0, off);
            s1 += __shfl_xor_sync(0xFFFFFFFFu, s1, off);
            s2 += __shfl_xor_sync(0xFFFFFFFFu, s2, off);
            s3 += __shfl_xor_sync(0xFFFFFFFFu, s3, off);
        }

        if (lane == 0) {
            float m = fminf(fminf(s0, s1), fminf(s2, s3));
            out[out_idx] = m * (1.0f / 256.0f);
        }

        pk = npk;
        sidx = npk & 0x3FFFF;
        a0 = na0; a1 = na1;
    }
}

// ---------------- fallback (direct gather) for B > MAXB ----------------

__global__ void __launch_bounds__(BDIM) direct_kernel(
    const float4* __restrict__ codes, const int* __restrict__ pred,
    const float4* __restrict__ cents, float* __restrict__ out, int B)
{
    const int warp = (int)((blockIdx.x * (unsigned)BDIM + threadIdx.x) >> 5);
    const int lane = threadIdx.x & 31;
    if (warp >= B) return;
    const float4* __restrict__ c = codes + (size_t)warp * D_F4;
    const float4 a0 = __ldg(&c[lane]);
    const float4 a1 = __ldg(&c[lane + 32]);
    int cls = clamp_cls(__ldg(&pred[warp]));
    const float4* __restrict__ ct = cents + (size_t)cls * (K_CENT * D_F4);
    float s[4];
    #pragma unroll
    for (int k = 0; k < 4; ++k) {
        float4 b0 = __ldg(&ct[k * D_F4 + lane]);
        float4 b1 = __ldg(&ct[k * D_F4 + lane + 32]);
        s[k] = fabsf(a0.x - b0.x) + fabsf(a0.y - b0.y) + fabsf(a0.z - b0.z) + fabsf(a0.w - b0.w)
             + fabsf(a1.x - b1.x) + fabsf(a1.y - b1.y) + fabsf(a1.z - b1.z) + fabsf(a1.w - b1.w);
    }
    #pragma unroll
    for (int off = 16; off > 0; off >>= 1) {
        s[0] += __shfl_xor_sync(0xFFFFFFFFu, s[0], off);
        s[1] += __shfl_xor_sync(0xFFFFFFFFu, s[1], off);
        s[2] += __shfl_xor_sync(0xFFFFFFFFu, s[2], off);
        s[3] += __shfl_xor_sync(0xFFFFFFFFu, s[3], off);
    }
    if (lane == 0)
        out[warp] = fminf(fminf(s[0], s[1]), fminf(s[2], s[3])) * (1.0f / 256.0f);
}

// ---------------- launch ----------------

extern "C" void kernel_launch(void* const* d_in, const int* in_sizes, int n_in,
                              void* d_out, int out_size)
{
    // Identify inputs by element count (order-proof):
    int i_codes = 0, i_pred = 0, i_cent = 0;
    for (int i = 1; i < n_in; ++i) {
        if (in_sizes[i] > in_sizes[i_codes]) i_codes = i;
        if (in_sizes[i] < in_sizes[i_pred])  i_pred  = i;
    }
    for (int i = 0; i < n_in; ++i)
        if (i != i_codes && i != i_pred) { i_cent = i; break; }

    const float4* codes = (const float4*)d_in[i_codes];
    const int*    pred  = (const int*)d_in[i_pred];
    const float4* cents = (const float4*)d_in[i_cent];
    float*        out   = (float*)d_out;
    const int B = in_sizes[i_pred];

    if (B > MAXB) {
        const int grid = (B + (BDIM / 32) - 1) / (BDIM / 32);
        direct_kernel<<<grid, BDIM>>>(codes, pred, cents, out, B);
        return;
    }

    const int nch = (B + CHUNK - 1) / CHUNK;     // <= 128
    // 1) per-chunk class histogram (non-atomic global store)
    hist_kernel<<<nch, BDIM>>>(pred, B);
    // 2) totals + exclusive scan + rewrite to per-(class,chunk) offsets
    scan_kernel<<<1, 1024>>>(nch);
    // 3) per-chunk scatter with smem cursors -> class-sorted packed perm
    scatter_kernel<<<nch, BDIM>>>(pred, B);
    // 4) main compute in sorted order
    const int warps = (B + SPW - 1) / SPW;
    const int grid  = (warps + (BDIM / 32) - 1) / (BDIM / 32);
    sorted_kernel<<<grid, BDIM>>>(codes, cents, out, B);
}

// round 10
// speedup vs baseline: 2.9024x; 2.9024x over previous
#include <cuda_runtime.h>
#include <cstdint>

#define BDIM      256
#define D_F4      64        // CODE_DIM/4
#define K_CENT    4
#define N_CLASSES 1000
#define MAXB      262144    // = 2^18; perm packs sidx in 18 bits
#define SPW       8         // sorted samples per warp in main kernel
#define CHUNK     2048
#define NCH_MAX   (MAXB / CHUNK)   // 128

// Scratch (static — no dynamic allocation allowed)
// g_hist[m][c]: chunk-major so scan/scatter accesses are coalesced across classes.
__device__ int g_hist[NCH_MAX][N_CLASSES];
__device__ int g_perm[MAXB];               // packed (cls<<18)|sidx, grouped by class

__device__ __forceinline__ int clamp_cls(int c) {
    return min(max(c, 0), N_CLASSES - 1);
}

// Folded warp reduction: sums s0..s3 over 32 lanes, returns min of the four
// totals in lane 0. 8 shuffles instead of 20.
__device__ __forceinline__ float warp_reduce4_min(float s0, float s1, float s2, float s3,
                                                  int lane) {
    const unsigned FULL = 0xFFFFFFFFu;
    const bool hi16 = (lane & 16);
    float t0 = hi16 ? s2 : s0;
    float o0 = hi16 ? s0 : s2;
    t0 += __shfl_xor_sync(FULL, o0, 16);
    float t1 = hi16 ? s3 : s1;
    float o1 = hi16 ? s1 : s3;
    t1 += __shfl_xor_sync(FULL, o1, 16);
    // lanes 0-15: t0 = s0-pairs, t1 = s1-pairs; lanes 16-31: t0 = s2, t1 = s3
    const bool hi8 = (lane & 8);
    float u = hi8 ? t1 : t0;
    float v = hi8 ? t0 : t1;
    u += __shfl_xor_sync(FULL, v, 8);
    // groups: 0-7 -> s0, 8-15 -> s1, 16-23 -> s2, 24-31 -> s3 (4-lane partials)
    u += __shfl_xor_sync(FULL, u, 4);
    u += __shfl_xor_sync(FULL, u, 2);
    u += __shfl_xor_sync(FULL, u, 1);
    // every lane in each 8-lane group holds that group's full sum
    float m = fminf(u, __shfl_xor_sync(FULL, u, 8));
    m = fminf(m, __shfl_xor_sync(FULL, m, 16));
    return m;   // lane 0: min(r0..r3)
}

// ---------------- pre-pass: radix-sort by class ----------------

__global__ void __launch_bounds__(BDIM) hist_kernel(const int* __restrict__ pred, int B) {
    __shared__ int h[N_CLASSES];
    for (int i = threadIdx.x; i < N_CLASSES; i += BDIM) h[i] = 0;
    __syncthreads();
    const int start = blockIdx.x * CHUNK;
    const int end   = min(start + CHUNK, B);
    for (int i = start + threadIdx.x; i < end; i += BDIM)
        atomicAdd(&h[clamp_cls(__ldg(&pred[i]))], 1);
    __syncthreads();
    for (int i = threadIdx.x; i < N_CLASSES; i += BDIM)
        g_hist[blockIdx.x][i] = h[i];          // coalesced store
}

// Single block: class totals -> exclusive scan of totals -> rewrite to offsets.
// All global accesses coalesced across threads (class index = thread index).
__global__ void __launch_bounds__(1024) scan_kernel(int nch) {
    __shared__ int s[1024];
    const int t = threadIdx.x;
    int total = 0;
    if (t < N_CLASSES)
        for (int m = 0; m < nch; ++m) total += g_hist[m][t];   // coalesced
    s[t] = (t < N_CLASSES) ? total : 0;
    __syncthreads();
    #pragma unroll
    for (int off = 1; off < 1024; off <<= 1) {
        int x = (t >= off) ? s[t - off] : 0;
        __syncthreads();
        s[t] += x;
        __syncthreads();
    }
    if (t < N_CLASSES) {
        int run = s[t] - total;                // exclusive class start
        for (int m = 0; m < nch; ++m) {
            int tmp = g_hist[m][t];
            g_hist[m][t] = run;                // coalesced rewrite
            run += tmp;
        }
    }
}

// Per-chunk scatter with SMEM cursors (atomics stay in smem).
__global__ void __launch_bounds__(BDIM) scatter_kernel(const int* __restrict__ pred, int B) {
    __shared__ int cur[N_CLASSES];
    const int b = blockIdx.x;
    for (int c = threadIdx.x; c < N_CLASSES; c += BDIM)
        cur[c] = g_hist[b][c];                 // coalesced load
    __syncthreads();
    const int start = b * CHUNK;
    const int end   = min(start + CHUNK, B);
    for (int i = start + threadIdx.x; i < end; i += BDIM) {
        int c = clamp_cls(__ldg(&pred[i]));
        int pos = atomicAdd(&cur[c], 1);
        g_perm[pos] = (c << 18) | i;
    }
}

// ---------------- main kernel (sorted, register-cached centroids, pipelined) ----

__global__ void __launch_bounds__(BDIM) sorted_kernel(
    const float4* __restrict__ codes,      // [B, 64]
    const float4* __restrict__ cents,      // [1000, 4, 64]
    float* __restrict__ out,               // [B]
    int B)
{
    const int warp = (int)((blockIdx.x * (unsigned)BDIM + threadIdx.x) >> 5);
    const int lane = threadIdx.x & 31;
    const int base = warp * SPW;
    if (base >= B) return;
    const int n = min(SPW, B - base);

    // one coalesced LDG fetches this warp's SPW perm entries; shfl broadcasts per j
    const int p = __ldg(&g_perm[base + min(lane, n - 1)]);

    float4 c00, c01, c10, c11, c20, c21, c30, c31;
    int cached = -1;

    // prefetch sample 0's codes
    int pk   = __shfl_sync(0xFFFFFFFFu, p, 0);
    int sidx = pk & 0x3FFFF;
    float4 a0, a1;
    {
        const float4* __restrict__ cp = codes + (size_t)sidx * D_F4;
        a0 = __ldg(&cp[lane]);
        a1 = __ldg(&cp[lane + 32]);
    }

    for (int j = 0; j < n; ++j) {
        const int cls     = pk >> 18;          // warp-uniform within sorted runs
        const int out_idx = sidx;

        // ---- prefetch next sample's codes before this sample's reduce ----
        int npk = pk;
        float4 na0 = a0, na1 = a1;
        if (j + 1 < n) {
            npk = __shfl_sync(0xFFFFFFFFu, p, j + 1);
            const int ns = npk & 0x3FFFF;
            const float4* __restrict__ np = codes + (size_t)ns * D_F4;
            na0 = __ldg(&np[lane]);
            na1 = __ldg(&np[lane + 32]);
        }

        // ---- centroid register cache (warp-uniform branch; rare reload) ----
        if (cls != cached) {
            const float4* __restrict__ ct = cents + (size_t)cls * (K_CENT * D_F4);
            c00 = __ldg(&ct[0 * D_F4 + lane]);  c01 = __ldg(&ct[0 * D_F4 + lane + 32]);
            c10 = __ldg(&ct[1 * D_F4 + lane]);  c11 = __ldg(&ct[1 * D_F4 + lane + 32]);
            c20 = __ldg(&ct[2 * D_F4 + lane]);  c21 = __ldg(&ct[2 * D_F4 + lane + 32]);
            c30 = __ldg(&ct[3 * D_F4 + lane]);  c31 = __ldg(&ct[3 * D_F4 + lane + 32]);
            cached = cls;
        }

        float s0 = fabsf(a0.x - c00.x) + fabsf(a0.y - c00.y) + fabsf(a0.z - c00.z) + fabsf(a0.w - c00.w)
                 + fabsf(a1.x - c01.x) + fabsf(a1.y - c01.y) + fabsf(a1.z - c01.z) + fabsf(a1.w - c01.w);
        float s1 = fabsf(a0.x - c10.x) + fabsf(a0.y - c10.y) + fabsf(a0.z - c10.z) + fabsf(a0.w - c10.w)
                 + fabsf(a1.x - c11.x) + fabsf(a1.y - c11.y) + fabsf(a1.z - c11.z) + fabsf(a1.w - c11.w);
        float s2 = fabsf(a0.x - c20.x) + fabsf(a0.y - c20.y) + fabsf(a0.z - c20.z) + fabsf(a0.w - c20.w)
                 + fabsf(a1.x - c21.x) + fabsf(a1.y - c21.y) + fabsf(a1.z - c21.z) + fabsf(a1.w - c21.w);
        float s3 = fabsf(a0.x - c30.x) + fabsf(a0.y - c30.y) + fabsf(a0.z - c30.z) + fabsf(a0.w - c30.w)
                 + fabsf(a1.x - c31.x) + fabsf(a1.y - c31.y) + fabsf(a1.z - c31.z) + fabsf(a1.w - c31.w);

        float m = warp_reduce4_min(s0, s1, s2, s3, lane);
        if (lane == 0)
            out[out_idx] = m * (1.0f / 256.0f);

        pk = npk;
        sidx = npk & 0x3FFFF;
        a0 = na0; a1 = na1;
    }
}

// ---------------- fallback (direct gather) for B > MAXB ----------------

__global__ void __launch_bounds__(BDIM) direct_kernel(
    const float4* __restrict__ codes, const int* __restrict__ pred,
    const float4* __restrict__ cents, float* __restrict__ out, int B)
{
    const int warp = (int)((blockIdx.x * (unsigned)BDIM + threadIdx.x) >> 5);
    const int lane = threadIdx.x & 31;
    if (warp >= B) return;
    const float4* __restrict__ c = codes + (size_t)warp * D_F4;
    const float4 a0 = __ldg(&c[lane]);
    const float4 a1 = __ldg(&c[lane + 32]);
    int cls = clamp_cls(__ldg(&pred[warp]));
    const float4* __restrict__ ct = cents + (size_t)cls * (K_CENT * D_F4);
    float s[4];
    #pragma unroll
    for (int k = 0; k < 4; ++k) {
        float4 b0 = __ldg(&ct[k * D_F4 + lane]);
        float4 b1 = __ldg(&ct[k * D_F4 + lane + 32]);
        s[k] = fabsf(a0.x - b0.x) + fabsf(a0.y - b0.y) + fabsf(a0.z - b0.z) + fabsf(a0.w - b0.w)
             + fabsf(a1.x - b1.x) + fabsf(a1.y - b1.y) + fabsf(a1.z - b1.z) + fabsf(a1.w - b1.w);
    }
    float m = warp_reduce4_min(s[0], s[1], s[2], s[3], lane);
    if (lane == 0)
        out[warp] = m * (1.0f / 256.0f);
}

// ---------------- launch ----------------

extern "C" void kernel_launch(void* const* d_in, const int* in_sizes, int n_in,
                              void* d_out, int out_size)
{
    // Identify inputs by element count (order-proof):
    int i_codes = 0, i_pred = 0, i_cent = 0;
    for (int i = 1; i < n_in; ++i) {
        if (in_sizes[i] > in_sizes[i_codes]) i_codes = i;
        if (in_sizes[i] < in_sizes[i_pred])  i_pred  = i;
    }
    for (int i = 0; i < n_in; ++i)
        if (i != i_codes && i != i_pred) { i_cent = i; break; }

    const float4* codes = (const float4*)d_in[i_codes];
    const int*    pred  = (const int*)d_in[i_pred];
    const float4* cents = (const float4*)d_in[i_cent];
    float*        out   = (float*)d_out;
    const int B = in_sizes[i_pred];

    if (B > MAXB) {
        const int grid = (B + (BDIM / 32) - 1) / (BDIM / 32);
        direct_kernel<<<grid, BDIM>>>(codes, pred, cents, out, B);
        return;
    }

    const int nch = (B + CHUNK - 1) / CHUNK;     // <= 128
    // 1) per-chunk class histogram (coalesced non-atomic global store)
    hist_kernel<<<nch, BDIM>>>(pred, B);
    // 2) totals + exclusive scan + rewrite to per-(chunk,class) offsets (coalesced)
    scan_kernel<<<1, 1024>>>(nch);
    // 3) per-chunk scatter with smem cursors -> class-sorted packed perm
    scatter_kernel<<<nch, BDIM>>>(pred, B);
    // 4) main compute in sorted order
    const int warps = (B + SPW - 1) / SPW;
    const int grid  = (warps + (BDIM / 32) - 1) / (BDIM / 32);
    sorted_kernel<<<grid, BDIM>>>(codes, cents, out, B);
}